// round 8
// baseline (speedup 1.0000x reference)
#include <cuda_runtime.h>
#include <cuda_fp16.h>
#include <cstdint>
#include <math.h>

#define B_      16
#define C_IN    512
#define C_OUT   512
#define HW_     4096
#define K_TOT   4608
#define STYLE_D 512

#define MOD_SCALE  0.04419417382415922f
#define CONV_SCALE 0.014731391274719738f
#define EPS_       1e-8f

// ---------------- device scratch (allocation-free rule) ----------------
__device__ float  g_s[B_ * C_IN];
__device__ float  g_wsq[C_OUT * C_IN];
__device__ float  g_demod[B_ * C_OUT];
__device__ __half g_A[(size_t)C_OUT * K_TOT];            // 4.7 MB fp16
__device__ __half g_X[(size_t)B_ * HW_ * K_TOT];         // 605 MB fp16 im2col

// ---------------- helpers ----------------
__device__ __forceinline__ uint32_t s2u(const void* p) {
    uint32_t a;
    asm("{ .reg .u64 t; cvta.to.shared.u64 t, %1; cvt.u32.u64 %0, t; }" : "=r"(a) : "l"(p));
    return a;
}
__device__ __forceinline__ void cp16(uint32_t dst, const void* src) {
    asm volatile("cp.async.cg.shared.global [%0], [%1], 16;" :: "r"(dst), "l"(src));
}
__device__ __forceinline__ void cp_commit() {
    asm volatile("cp.async.commit_group;");
}
template <int N>
__device__ __forceinline__ void cp_wait() {
    asm volatile("cp.async.wait_group %0;" :: "n"(N));
}

// mma.sync m16n8k16 f16->f32 (sm_80+, valid on plain compute_103 target)
__device__ __forceinline__ void mma16(float* d, const uint32_t* a, const uint32_t* b) {
    asm volatile(
        "mma.sync.aligned.m16n8k16.row.col.f32.f16.f16.f32 "
        "{%0,%1,%2,%3}, {%4,%5,%6,%7}, {%8,%9}, {%0,%1,%2,%3};"
        : "+f"(d[0]), "+f"(d[1]), "+f"(d[2]), "+f"(d[3])
        : "r"(a[0]), "r"(a[1]), "r"(a[2]), "r"(a[3]), "r"(b[0]), "r"(b[1]));
}

// ---------------------------------------------------------------------------
// K0: s[b,ci] = style @ (modw*MOD_SCALE)^T + bias
// ---------------------------------------------------------------------------
__global__ void style_kernel(const float* __restrict__ style,
                             const float* __restrict__ modw,
                             const float* __restrict__ modb) {
    int b = blockIdx.x, ci = threadIdx.x;
    __shared__ float st[STYLE_D];
    st[ci] = style[b * STYLE_D + ci];
    __syncthreads();
    const float* wr = modw + (size_t)ci * STYLE_D;
    float acc = 0.f;
#pragma unroll 8
    for (int d = 0; d < STYLE_D; d++) acc += st[d] * wr[d];
    g_s[b * C_IN + ci] = acc * MOD_SCALE + modb[ci];
}

// ---------------------------------------------------------------------------
// K1: wsq[co,ci] = sum_k W^2   (fp32 path for exact demod)
// ---------------------------------------------------------------------------
__global__ void wsq_kernel(const float* __restrict__ w) {
    int i = blockIdx.x * blockDim.x + threadIdx.x;
    if (i < C_OUT * C_IN) {
        const float* p = w + (size_t)i * 9;
        float a = 0.f;
#pragma unroll
        for (int k = 0; k < 9; k++) a += p[k] * p[k];
        g_wsq[i] = a;
    }
}

// ---------------------------------------------------------------------------
// K2: demod[b,co] = rsqrt(CONV_SCALE^2 * sum_ci s^2*wsq + eps)
// ---------------------------------------------------------------------------
__global__ void demod_kernel() {
    int b = blockIdx.x, co = threadIdx.x;
    __shared__ float s2[C_IN];
    float sv = g_s[b * C_IN + co];
    s2[co] = sv * sv;
    __syncthreads();
    const float* q = g_wsq + (size_t)co * C_IN;
    float a = 0.f;
#pragma unroll 8
    for (int ci = 0; ci < C_IN; ci++) a += s2[ci] * q[ci];
    g_demod[b * C_OUT + co] = rsqrtf(a * (CONV_SCALE * CONV_SCALE) + EPS_);
}

// ---------------------------------------------------------------------------
// K3: A[co][K], K = k*512+ci, fp16
// ---------------------------------------------------------------------------
__global__ void apack_kernel(const float* __restrict__ w) {
    int co = blockIdx.y;
    int Kp = blockIdx.x * 256 + threadIdx.x;
    int k = Kp >> 9, ci = Kp & 511;
    g_A[(size_t)co * K_TOT + Kp] = __float2half_rn(w[((size_t)co * 512 + ci) * 9 + k]);
}

// ---------------------------------------------------------------------------
// K4: im2col fp16. g_X[b][y*64+x][k*512+ci] = h(input[b,ci,y+kh-1,x+kw-1]*s)
// grid (16 cig, 64 y, 16 b), block 256
// ---------------------------------------------------------------------------
__global__ __launch_bounds__(256) void im2col_kernel(const float* __restrict__ input) {
    const int ci0 = blockIdx.x * 32;
    const int y   = blockIdx.y;
    const int b   = blockIdx.z;
    const int t   = threadIdx.x;
    __shared__ float In3[32][3][68];
    __shared__ float sS[32];
    if (t < 32) sS[t] = g_s[b * C_IN + ci0 + t];
    __syncthreads();
    for (int idx = t; idx < 32 * 3 * 66; idx += 256) {
        int ci = idx / 198, r = idx % 198, dy = r / 66, xx = r % 66;
        int ys = y + dy - 1, xs = xx - 1;
        float v = 0.f;
        if ((unsigned)ys < 64 && (unsigned)xs < 64)
            v = input[(((size_t)b * C_IN + ci0 + ci) * 64 + ys) * 64 + xs] * sS[ci];
        In3[ci][dy][xx] = v;
    }
    __syncthreads();
    const size_t rowbase = (size_t)b * HW_ + y * 64;
#pragma unroll
    for (int k = 0; k < 9; k++) {
        const int kh = k / 3, kw = k % 3;
#pragma unroll
        for (int rep = 0; rep < 4; rep++) {
            int idx = rep * 256 + t;       // 0..1023
            int x  = idx >> 4;             // 0..63
            int ip = idx & 15;             // half2 pair index
            __half2 v = __floats2half2_rn(In3[ip * 2][kh][x + kw],
                                          In3[ip * 2 + 1][kh][x + kw]);
            *(__half2*)&g_X[(rowbase + x) * K_TOT + k * 512 + ci0 + ip * 2] = v;
        }
    }
}

// ---------------------------------------------------------------------------
// K5: GEMM fp16 mma.sync. CTA: M=128 co x N=128 px, K=4608 in 144 chunks of 32.
// 8 warps (2 M x 4 N), warp tile 64x32, two k16 steps per chunk.
// smem rows: 32 halves payload, stride 40 halves (80 B) -> cp16-aligned and
// conflict-free half2 fragment loads. 8-stage cp.async ring.
// ---------------------------------------------------------------------------
#define RSH       40                       // row stride in halves (80 B)
#define TILE_B    (128 * RSH * 2)          // 10240 B per operand tile
#define STAGE_B   (2 * TILE_B)             // 20480 B
#define NSTAGE    8
#define NS        144
#define DYN_SMEM  (NSTAGE * STAGE_B)       // 163840 B

__global__ __launch_bounds__(256, 1) void gemm_kernel(float* __restrict__ out) {
    extern __shared__ __half smem[];
    const uint32_t sb = s2u(smem);
    const int t = threadIdx.x;
    const int w = t >> 5, lane = t & 31;
    const int mw = w >> 2;        // 0..1
    const int nw = w & 3;         // 0..3
    const int lr = lane >> 2;     // 0..7
    const int lc = lane & 3;      // 0..3

    const int co0 = blockIdx.x * 128;   // co fastest -> X-sharing CTAs adjacent
    const int p0  = blockIdx.y * 128;
    const int b   = blockIdx.z;

    const __half* Ab = g_A + (size_t)co0 * K_TOT;
    const __half* Xb = g_X + ((size_t)b * HW_ + p0) * K_TOT;

    // 1024 cp16 chunks per stage: A 512 + X 512, 4 per thread
    auto load_stage = [&](int stage) {
        const uint32_t base = sb + (stage & (NSTAGE - 1)) * STAGE_B;
        const int koff = stage * 32;
#pragma unroll
        for (int j = 0; j < 2; j++) {
            int idx = j * 256 + t;          // 0..511
            int row = idx >> 2, ch = (idx & 3) * 8;
            cp16(base + row * 80 + ch * 2, Ab + (size_t)row * K_TOT + koff + ch);
        }
#pragma unroll
        for (int j = 0; j < 2; j++) {
            int idx = j * 256 + t;
            int row = idx >> 2, ch = (idx & 3) * 8;
            cp16(base + TILE_B + row * 80 + ch * 2, Xb + (size_t)row * K_TOT + koff + ch);
        }
        cp_commit();
    };

    float acc[4][4][4];
#pragma unroll
    for (int i = 0; i < 4; i++)
#pragma unroll
        for (int j = 0; j < 4; j++)
#pragma unroll
            for (int c = 0; c < 4; c++) acc[i][j][c] = 0.f;

#pragma unroll
    for (int s = 0; s < NSTAGE - 1; s++) load_stage(s);

    for (int i = 0; i < NS; i++) {
        cp_wait<NSTAGE - 2>();
        __syncthreads();
        if (i + NSTAGE - 1 < NS) load_stage(i + NSTAGE - 1);

        const __half* As = smem + (i & (NSTAGE - 1)) * (STAGE_B / 2);
        const __half* Bs = As + (TILE_B / 2);

#pragma unroll
        for (int ks = 0; ks < 2; ks++) {
            const int kc = ks * 16 + lc * 2;
            uint32_t af[4][4], bf[4][2];
#pragma unroll
            for (int mf = 0; mf < 4; mf++) {
                const int r0 = mw * 64 + mf * 16 + lr;
                af[mf][0] = *(const uint32_t*)&As[r0 * RSH + kc];
                af[mf][1] = *(const uint32_t*)&As[(r0 + 8) * RSH + kc];
                af[mf][2] = *(const uint32_t*)&As[r0 * RSH + kc + 8];
                af[mf][3] = *(const uint32_t*)&As[(r0 + 8) * RSH + kc + 8];
            }
#pragma unroll
            for (int nf = 0; nf < 4; nf++) {
                const int pr = nw * 32 + nf * 8 + lr;
                bf[nf][0] = *(const uint32_t*)&Bs[pr * RSH + kc];
                bf[nf][1] = *(const uint32_t*)&Bs[pr * RSH + kc + 8];
            }
#pragma unroll
            for (int mf = 0; mf < 4; mf++)
#pragma unroll
                for (int nf = 0; nf < 4; nf++)
                    mma16(acc[mf][nf], af[mf], bf[nf]);
        }
        __syncthreads();
    }

    // ---- epilogue: scale by demod*CONV_SCALE, write float2 ----
#pragma unroll
    for (int mf = 0; mf < 4; mf++) {
        const int coA = co0 + mw * 64 + mf * 16 + lr;
        const int coB = coA + 8;
        const float scA = g_demod[b * C_OUT + coA] * CONV_SCALE;
        const float scB = g_demod[b * C_OUT + coB] * CONV_SCALE;
        float* opA = out + ((size_t)b * C_OUT + coA) * HW_ + p0;
        float* opB = out + ((size_t)b * C_OUT + coB) * HW_ + p0;
#pragma unroll
        for (int nf = 0; nf < 4; nf++) {
            const int px = nw * 32 + nf * 8 + lc * 2;
            float2 vA, vB;
            vA.x = acc[mf][nf][0] * scA; vA.y = acc[mf][nf][1] * scA;
            vB.x = acc[mf][nf][2] * scB; vB.y = acc[mf][nf][3] * scB;
            *(float2*)(opA + px) = vA;
            *(float2*)(opB + px) = vB;
        }
    }
}

// ---------------------------------------------------------------------------
extern "C" void kernel_launch(void* const* d_in, const int* in_sizes, int n_in,
                              void* d_out, int out_size) {
    const float* input = (const float*)d_in[0];
    const float* style = (const float*)d_in[1];
    const float* convw = (const float*)d_in[2];
    const float* modw  = (const float*)d_in[3];
    const float* modb  = (const float*)d_in[4];
    float* out = (float*)d_out;

    static int init_done = 0;
    if (!init_done) {
        cudaFuncSetAttribute(gemm_kernel, cudaFuncAttributeMaxDynamicSharedMemorySize, DYN_SMEM);
        init_done = 1;
    }

    style_kernel<<<B_, STYLE_D>>>(style, modw, modb);
    wsq_kernel<<<(C_OUT * C_IN + 511) / 512, 512>>>(convw);
    demod_kernel<<<B_, C_OUT>>>();
    apack_kernel<<<dim3(18, C_OUT), 256>>>(convw);
    im2col_kernel<<<dim3(16, 64, B_), 256>>>(input);
    gemm_kernel<<<dim3(4, 32, 16), 256, DYN_SMEM>>>(out);
}

// round 9
// speedup vs baseline: 1.2417x; 1.2417x over previous
#include <cuda_runtime.h>
#include <cstdint>
#include <math.h>

#define B_      16
#define C_IN    512
#define C_OUT   512
#define HW_     4096
#define K_TOT   4608
#define STYLE_D 512

#define MOD_SCALE  0.04419417382415922f
#define CONV_SCALE 0.014731391274719738f
#define EPS_       1e-8f

// ---------------- device scratch (allocation-free rule) ----------------
__device__ float g_s[B_ * C_IN];
__device__ float g_wsq[C_OUT * C_IN];
__device__ float g_demod[B_ * C_OUT];
__device__ float g_A[(size_t)C_OUT * K_TOT];            // 9.4 MB tf32
__device__ float g_X[(size_t)B_ * HW_ * K_TOT];         // 1.21 GB im2col tf32

// ---------------- helpers ----------------
__device__ __forceinline__ float to_tf32(float v) {
    asm("cvt.rna.tf32.f32 %0, %0;" : "+f"(v));
    return v;
}
__device__ __forceinline__ uint32_t s2u(const void* p) {
    uint32_t a;
    asm("{ .reg .u64 t; cvta.to.shared.u64 t, %1; cvt.u32.u64 %0, t; }" : "=r"(a) : "l"(p));
    return a;
}
__device__ __forceinline__ void cp16(uint32_t dst, const void* src) {
    asm volatile("cp.async.cg.shared.global [%0], [%1], 16;" :: "r"(dst), "l"(src));
}
__device__ __forceinline__ void cp_commit() {
    asm volatile("cp.async.commit_group;");
}
template <int N>
__device__ __forceinline__ void cp_wait() {
    asm volatile("cp.async.wait_group %0;" :: "n"(N));
}

// mma.sync m16n8k8 tf32 (sm_80+, valid on plain compute_103 target)
__device__ __forceinline__ void mma8(float* d, const uint32_t* a, const uint32_t* b) {
    asm volatile(
        "mma.sync.aligned.m16n8k8.row.col.f32.tf32.tf32.f32 "
        "{%0,%1,%2,%3}, {%4,%5,%6,%7}, {%8,%9}, {%0,%1,%2,%3};"
        : "+f"(d[0]), "+f"(d[1]), "+f"(d[2]), "+f"(d[3])
        : "r"(a[0]), "r"(a[1]), "r"(a[2]), "r"(a[3]), "r"(b[0]), "r"(b[1]));
}

// ---------------------------------------------------------------------------
// K0: s[b,ci]
// ---------------------------------------------------------------------------
__global__ void style_kernel(const float* __restrict__ style,
                             const float* __restrict__ modw,
                             const float* __restrict__ modb) {
    int b = blockIdx.x, ci = threadIdx.x;
    __shared__ float st[STYLE_D];
    st[ci] = style[b * STYLE_D + ci];
    __syncthreads();
    const float* wr = modw + (size_t)ci * STYLE_D;
    float acc = 0.f;
#pragma unroll 8
    for (int d = 0; d < STYLE_D; d++) acc += st[d] * wr[d];
    g_s[b * C_IN + ci] = acc * MOD_SCALE + modb[ci];
}

// ---------------------------------------------------------------------------
// K1: wsq[co,ci] = sum_k W^2
// ---------------------------------------------------------------------------
__global__ void wsq_kernel(const float* __restrict__ w) {
    int i = blockIdx.x * blockDim.x + threadIdx.x;
    if (i < C_OUT * C_IN) {
        const float* p = w + (size_t)i * 9;
        float a = 0.f;
#pragma unroll
        for (int k = 0; k < 9; k++) a += p[k] * p[k];
        g_wsq[i] = a;
    }
}

// ---------------------------------------------------------------------------
// K2: demod[b,co]
// ---------------------------------------------------------------------------
__global__ void demod_kernel() {
    int b = blockIdx.x, co = threadIdx.x;
    __shared__ float s2[C_IN];
    float sv = g_s[b * C_IN + co];
    s2[co] = sv * sv;
    __syncthreads();
    const float* q = g_wsq + (size_t)co * C_IN;
    float a = 0.f;
#pragma unroll 8
    for (int ci = 0; ci < C_IN; ci++) a += s2[ci] * q[ci];
    g_demod[b * C_OUT + co] = rsqrtf(a * (CONV_SCALE * CONV_SCALE) + EPS_);
}

// ---------------------------------------------------------------------------
// K3: A[co][K], K = k*512+ci, tf32-rounded
// ---------------------------------------------------------------------------
__global__ void apack_kernel(const float* __restrict__ w) {
    int co = blockIdx.y;
    int Kp = blockIdx.x * 256 + threadIdx.x;
    int k = Kp >> 9, ci = Kp & 511;
    g_A[(size_t)co * K_TOT + Kp] = to_tf32(w[((size_t)co * 512 + ci) * 9 + k]);
}

// ---------------------------------------------------------------------------
// K4: im2col. g_X[b][y*64+x][k*512+ci] = tf32(input[b,ci,y+kh-1,x+kw-1]*s)
// ---------------------------------------------------------------------------
__global__ __launch_bounds__(256) void im2col_kernel(const float* __restrict__ input) {
    const int ci0 = blockIdx.x * 32;
    const int y   = blockIdx.y;
    const int b   = blockIdx.z;
    const int t   = threadIdx.x;
    __shared__ float In3[32][3][68];
    __shared__ float sS[32];
    if (t < 32) sS[t] = g_s[b * C_IN + ci0 + t];
    __syncthreads();
    for (int idx = t; idx < 32 * 3 * 66; idx += 256) {
        int ci = idx / 198, r = idx % 198, dy = r / 66, xx = r % 66;
        int ys = y + dy - 1, xs = xx - 1;
        float v = 0.f;
        if ((unsigned)ys < 64 && (unsigned)xs < 64)
            v = input[(((size_t)b * C_IN + ci0 + ci) * 64 + ys) * 64 + xs] * sS[ci];
        In3[ci][dy][xx] = to_tf32(v);
    }
    __syncthreads();
    const size_t rowbase = (size_t)b * HW_ + y * 64;
#pragma unroll
    for (int k = 0; k < 9; k++) {
        const int kh = k / 3, kw = k % 3;
#pragma unroll
        for (int rep = 0; rep < 8; rep++) {
            int idx = rep * 256 + t;
            int x = idx >> 5, i = idx & 31;
            g_X[(rowbase + x) * K_TOT + k * 512 + ci0 + i] = In3[i][kh][x + kw];
        }
    }
}

// ---------------------------------------------------------------------------
// K5: GEMM tf32 mma.sync. CTA: M=128 co x N=128 px, K=4608, 144 stages of 32.
// 8 warps (2 M x 4 N), warp tile 64x32. 3-stage cp.async ring, 2 CTAs/SM.
// smem row: 32 K floats + 4 pad (stride 36 floats = 144 B).
// ---------------------------------------------------------------------------
#define RS        36
#define TILE_B    (128 * RS * 4)       // 18432 B per operand tile
#define STAGE_B   (2 * TILE_B)         // 36864 B
#define NSTAGE    3
#define NS        144
#define DYN_SMEM  (NSTAGE * STAGE_B)   // 110592 B -> 2 CTAs/SM

__global__ __launch_bounds__(256, 2) void gemm_kernel(float* __restrict__ out) {
    extern __shared__ float smem[];
    const uint32_t sb = s2u(smem);
    const int t = threadIdx.x;
    const int w = t >> 5, lane = t & 31;
    const int mw = w >> 2;        // 0..1  (M warp row)
    const int nw = w & 3;         // 0..3  (N warp col)
    const int lr = lane >> 2;     // 0..7
    const int lc = lane & 3;      // 0..3

    const int co0 = blockIdx.x * 128;   // co fastest -> X-sharing CTAs adjacent
    const int p0  = blockIdx.y * 128;
    const int b   = blockIdx.z;

    const float* Ab = g_A + (size_t)co0 * K_TOT;
    const float* Xb = g_X + ((size_t)b * HW_ + p0) * K_TOT;

    auto load_stage = [&](int stage, int buf) {
        const uint32_t base = sb + buf * STAGE_B;
        const int koff = stage * 32;
#pragma unroll
        for (int j = 0; j < 4; j++) {
            int idx = j * 256 + t;          // 0..1023
            int row = idx >> 3, ch = (idx & 7) * 4;
            cp16(base + (row * RS + ch) * 4, Ab + (size_t)row * K_TOT + koff + ch);
        }
#pragma unroll
        for (int j = 0; j < 4; j++) {
            int idx = j * 256 + t;
            int row = idx >> 3, ch = (idx & 7) * 4;
            cp16(base + TILE_B + (row * RS + ch) * 4, Xb + (size_t)row * K_TOT + koff + ch);
        }
        cp_commit();
    };

    float acc[4][4][4];
#pragma unroll
    for (int i = 0; i < 4; i++)
#pragma unroll
        for (int j = 0; j < 4; j++)
#pragma unroll
            for (int c = 0; c < 4; c++) acc[i][j][c] = 0.f;

    load_stage(0, 0);
    load_stage(1, 1);

    int bufc = 0;   // buffer of current compute stage
    for (int i = 0; i < NS; i++) {
        cp_wait<1>();
        __syncthreads();
        if (i + 2 < NS) {
            int nb = bufc + 2; if (nb >= NSTAGE) nb -= NSTAGE;
            load_stage(i + 2, nb);
        }

        const float* As = smem + bufc * (STAGE_B / 4);
        const float* Bs = As + (TILE_B / 4);

#pragma unroll
        for (int ks = 0; ks < 4; ks++) {
            const int kc = ks * 8 + lc;
            uint32_t af[4][4], bf[4][2];
#pragma unroll
            for (int mf = 0; mf < 4; mf++) {
                const int r0 = mw * 64 + mf * 16 + lr;
                af[mf][0] = __float_as_uint(As[r0 * RS + kc]);
                af[mf][1] = __float_as_uint(As[(r0 + 8) * RS + kc]);
                af[mf][2] = __float_as_uint(As[r0 * RS + kc + 4]);
                af[mf][3] = __float_as_uint(As[(r0 + 8) * RS + kc + 4]);
            }
#pragma unroll
            for (int nf = 0; nf < 4; nf++) {
                const int pr = nw * 32 + nf * 8 + lr;
                bf[nf][0] = __float_as_uint(Bs[pr * RS + kc]);
                bf[nf][1] = __float_as_uint(Bs[pr * RS + kc + 4]);
            }
#pragma unroll
            for (int mf = 0; mf < 4; mf++)
#pragma unroll
                for (int nf = 0; nf < 4; nf++)
                    mma8(acc[mf][nf], af[mf], bf[nf]);
        }
        __syncthreads();
        bufc = (bufc + 1 == NSTAGE) ? 0 : bufc + 1;
    }

    // ---- epilogue: scale by demod*CONV_SCALE, write float2 ----
#pragma unroll
    for (int mf = 0; mf < 4; mf++) {
        const int coA = co0 + mw * 64 + mf * 16 + lr;
        const int coB = coA + 8;
        const float scA = g_demod[b * C_OUT + coA] * CONV_SCALE;
        const float scB = g_demod[b * C_OUT + coB] * CONV_SCALE;
        float* opA = out + ((size_t)b * C_OUT + coA) * HW_ + p0;
        float* opB = out + ((size_t)b * C_OUT + coB) * HW_ + p0;
#pragma unroll
        for (int nf = 0; nf < 4; nf++) {
            const int px = nw * 32 + nf * 8 + lc * 2;
            float2 vA, vB;
            vA.x = acc[mf][nf][0] * scA; vA.y = acc[mf][nf][1] * scA;
            vB.x = acc[mf][nf][2] * scB; vB.y = acc[mf][nf][3] * scB;
            *(float2*)(opA + px) = vA;
            *(float2*)(opB + px) = vB;
        }
    }
}

// ---------------------------------------------------------------------------
extern "C" void kernel_launch(void* const* d_in, const int* in_sizes, int n_in,
                              void* d_out, int out_size) {
    const float* input = (const float*)d_in[0];
    const float* style = (const float*)d_in[1];
    const float* convw = (const float*)d_in[2];
    const float* modw  = (const float*)d_in[3];
    const float* modb  = (const float*)d_in[4];
    float* out = (float*)d_out;

    static int init_done = 0;
    if (!init_done) {
        cudaFuncSetAttribute(gemm_kernel, cudaFuncAttributeMaxDynamicSharedMemorySize, DYN_SMEM);
        init_done = 1;
    }

    style_kernel<<<B_, STYLE_D>>>(style, modw, modb);
    wsq_kernel<<<(C_OUT * C_IN + 511) / 512, 512>>>(convw);
    demod_kernel<<<B_, C_OUT>>>();
    apack_kernel<<<dim3(18, C_OUT), 256>>>(convw);
    im2col_kernel<<<dim3(16, 64, B_), 256>>>(input);
    gemm_kernel<<<dim3(4, 32, 16), 256, DYN_SMEM>>>(out);
}

// round 12
// speedup vs baseline: 1.4246x; 1.1474x over previous
#include <cuda_runtime.h>
#include <cstdint>
#include <math.h>

#define B_      16
#define C_IN    512
#define C_OUT   512
#define HW_     4096
#define K_TOT   4608
#define STYLE_D 512

#define MOD_SCALE  0.04419417382415922f
#define CONV_SCALE 0.014731391274719738f
#define EPS_       1e-8f

// ---------------- device scratch ----------------
__device__ float g_s[B_ * C_IN];
__device__ float g_wsq[C_OUT * C_IN];
__device__ float g_demod[B_ * C_OUT];
// A_perm: [ct 4][s 144][4096 floats]  (fragment-ordered, tf32-rounded)
__device__ float g_A[(size_t)4 * 144 * 4096];
// X_perm: [b 16][pt 16][s 144][8192 floats] (fragment-ordered, tf32-rounded)
__device__ float g_X[(size_t)B_ * 16 * 144 * 8192];

// ---------------- helpers ----------------
__device__ __forceinline__ float to_tf32(float v) {
    asm("cvt.rna.tf32.f32 %0, %0;" : "+f"(v));
    return v;
}
__device__ __forceinline__ uint32_t s2u(const void* p) {
    uint32_t a;
    asm("{ .reg .u64 t; cvta.to.shared.u64 t, %1; cvt.u32.u64 %0, t; }" : "=r"(a) : "l"(p));
    return a;
}
__device__ __forceinline__ void cp16(uint32_t dst, const void* src) {
    asm volatile("cp.async.cg.shared.global [%0], [%1], 16;" :: "r"(dst), "l"(src));
}
__device__ __forceinline__ void cp_commit() {
    asm volatile("cp.async.commit_group;");
}
template <int N>
__device__ __forceinline__ void cp_wait() {
    asm volatile("cp.async.wait_group %0;" :: "n"(N));
}
__device__ __forceinline__ void mma8(float* d, const uint32_t* a, const uint32_t* b) {
    asm volatile(
        "mma.sync.aligned.m16n8k8.row.col.f32.tf32.tf32.f32 "
        "{%0,%1,%2,%3}, {%4,%5,%6,%7}, {%8,%9}, {%0,%1,%2,%3};"
        : "+f"(d[0]), "+f"(d[1]), "+f"(d[2]), "+f"(d[3])
        : "r"(a[0]), "r"(a[1]), "r"(a[2]), "r"(a[3]), "r"(b[0]), "r"(b[1]));
}

// ---------------------------------------------------------------------------
// K0: s[b,ci]
// ---------------------------------------------------------------------------
__global__ void style_kernel(const float* __restrict__ style,
                             const float* __restrict__ modw,
                             const float* __restrict__ modb) {
    int b = blockIdx.x, ci = threadIdx.x;
    __shared__ float st[STYLE_D];
    st[ci] = style[b * STYLE_D + ci];
    __syncthreads();
    const float* wr = modw + (size_t)ci * STYLE_D;
    float acc = 0.f;
#pragma unroll 8
    for (int d = 0; d < STYLE_D; d++) acc += st[d] * wr[d];
    g_s[b * C_IN + ci] = acc * MOD_SCALE + modb[ci];
}

// ---------------------------------------------------------------------------
// K1: wsq[co,ci] = sum_k W^2
// ---------------------------------------------------------------------------
__global__ void wsq_kernel(const float* __restrict__ w) {
    int i = blockIdx.x * blockDim.x + threadIdx.x;
    if (i < C_OUT * C_IN) {
        const float* p = w + (size_t)i * 9;
        float a = 0.f;
#pragma unroll
        for (int k = 0; k < 9; k++) a += p[k] * p[k];
        g_wsq[i] = a;
    }
}

// ---------------------------------------------------------------------------
// K2: demod[b,co]
// ---------------------------------------------------------------------------
__global__ void demod_kernel() {
    int b = blockIdx.x, co = threadIdx.x;
    __shared__ float s2[C_IN];
    float sv = g_s[b * C_IN + co];
    s2[co] = sv * sv;
    __syncthreads();
    const float* q = g_wsq + (size_t)co * C_IN;
    float a = 0.f;
#pragma unroll 8
    for (int ci = 0; ci < C_IN; ci++) a += s2[ci] * q[ci];
    g_demod[b * C_OUT + co] = rsqrtf(a * (CONV_SCALE * CONV_SCALE) + EPS_);
}

// ---------------------------------------------------------------------------
// K3: A_perm. block of 4096 floats per (ct,s): [ks 4][mh 2][mf 4][lane 32][e 4]
//   lr=lane>>2, lc=lane&3; kc=ks*8+lc+(e>>1)*4; row=mh*64+mf*16+lr+(e&1)*8
//   co=ct*128+row; K=s*32+kc; k=K>>9; ci=K&511
// grid 2304, block 256, 4 floats/thread (one float4 store)
// ---------------------------------------------------------------------------
__global__ void apack_kernel(const float* __restrict__ w) {
    size_t idx = ((size_t)blockIdx.x * 256 + threadIdx.x) * 4;
    int within = (int)(idx & 4095);
    int blkid  = (int)(idx >> 12);
    int s  = blkid % 144;
    int ct = blkid / 144;
    int lane = (within >> 2) & 31;
    int mf   = (within >> 7) & 3;
    int mh   = (within >> 9) & 1;
    int ks   = within >> 10;
    int lr = lane >> 2, lc = lane & 3;
    float4 v;
#pragma unroll
    for (int e = 0; e < 4; e++) {
        int kc  = ks * 8 + lc + (e >> 1) * 4;
        int row = mh * 64 + mf * 16 + lr + (e & 1) * 8;
        int co  = ct * 128 + row;
        int K   = s * 32 + kc;
        int k = K >> 9, ci = K & 511;
        ((float*)&v)[e] = to_tf32(w[((size_t)co * 512 + ci) * 9 + k]);
    }
    *(float4*)&g_A[idx] = v;
}

// ---------------------------------------------------------------------------
// K4: im2col -> X_perm. block = (ci0 group 32, y row, b).
// stage s = k*16 + ci0/32; pt = y>>2; nw = y&3 (fragment quadrant).
// block of 8192 floats per (b,pt,s): [ks 4][nw 4][nf 8][lane 32][e 2]
//   pr = nw*64 + nf*8 + lr ; kc = ks*8 + lc + e*4
// ---------------------------------------------------------------------------
__global__ __launch_bounds__(256) void im2col_kernel(const float* __restrict__ input) {
    const int ci0 = blockIdx.x * 32;
    const int y   = blockIdx.y;
    const int b   = blockIdx.z;
    const int t   = threadIdx.x;
    __shared__ float In3[32][3][68];
    __shared__ float sS[32];
    if (t < 32) sS[t] = g_s[b * C_IN + ci0 + t];
    __syncthreads();
    for (int idx = t; idx < 32 * 3 * 66; idx += 256) {
        int ci = idx / 198, r = idx % 198, dy = r / 66, xx = r % 66;
        int ys = y + dy - 1, xs = xx - 1;
        float v = 0.f;
        if ((unsigned)ys < 64 && (unsigned)xs < 64)
            v = input[(((size_t)b * C_IN + ci0 + ci) * 64 + ys) * 64 + xs] * sS[ci];
        In3[ci][dy][xx] = to_tf32(v);
    }
    __syncthreads();

    const int pt = y >> 2;
    const int nw = y & 3;
#pragma unroll
    for (int k = 0; k < 9; k++) {
        const int kh = k / 3, kw = k % 3;
        const int s = k * 16 + (ci0 >> 5);
        float* base = g_X + (((size_t)(b * 16 + pt) * 144) + s) * 8192;
#pragma unroll
        for (int rep = 0; rep < 8; rep++) {
            int idx = rep * 256 + t;       // 0..2047: x = idx>>5, ci = idx&31
            int x  = idx >> 5;
            int ci = idx & 31;
            int ks = ci >> 3, r2 = ci & 7;
            int lc = r2 & 3, e = r2 >> 2;
            int nf = x >> 3, lr = x & 7;
            int lane = lr * 4 + lc;
            int fidx = (((ks * 4 + nw) * 8 + nf) * 32 + lane) * 2 + e;
            base[fidx] = In3[ci][kh][x + kw];
        }
    }
}

// ---------------------------------------------------------------------------
// K5: GEMM tf32. CTA: M=128 co x N=256 px, 8 warps (2 M x 4 N), warp 64x64.
// K=4608 in 144 stages of 32. 3-stage cp.async ring, fragment-ordered smem:
// A stage 16KB (LDS.128 frags), B stage 32KB (LDS.64 frags). 1 CTA/SM.
// ---------------------------------------------------------------------------
#define A_STAGE_B 16384
#define B_STAGE_B 32768
#define STAGE_B   (A_STAGE_B + B_STAGE_B)   // 49152
#define NSTAGE    3
#define NS        144
#define DYN_SMEM  (NSTAGE * STAGE_B)        // 147456

__global__ __launch_bounds__(256, 1) void gemm_kernel(float* __restrict__ out) {
    extern __shared__ float smem[];
    const uint32_t sb = s2u(smem);
    const int t = threadIdx.x;
    const int w = t >> 5, lane = t & 31;
    const int mw = w >> 2;        // 0..1
    const int nw = w & 3;         // 0..3
    const int lr = lane >> 2;     // 0..7
    const int lc = lane & 3;      // 0..3

    const int ct = blockIdx.x;          // co tile (co fastest)
    const int pt = blockIdx.y;          // 256-px tile
    const int b  = blockIdx.z;

    const float* Ab = g_A + (size_t)ct * 144 * 4096;
    const float* Xb = g_X + ((size_t)(b * 16 + pt) * 144) * 8192;

    // 3072 cp16 chunks per stage (A 1024 + B 2048), 12 per thread, linear copy
    auto load_stage = [&](int stage, int buf) {
        const uint32_t base = sb + buf * STAGE_B;
        const float* as = Ab + (size_t)stage * 4096;
        const float* xs = Xb + (size_t)stage * 8192;
#pragma unroll
        for (int j = 0; j < 4; j++) {
            int c = j * 256 + t;
            cp16(base + c * 16, as + c * 4);
        }
#pragma unroll
        for (int j = 0; j < 8; j++) {
            int c = j * 256 + t;
            cp16(base + A_STAGE_B + c * 16, xs + c * 4);
        }
        cp_commit();
    };

    float acc[4][8][4];
#pragma unroll
    for (int i = 0; i < 4; i++)
#pragma unroll
        for (int j = 0; j < 8; j++)
#pragma unroll
            for (int c = 0; c < 4; c++) acc[i][j][c] = 0.f;

    load_stage(0, 0);
    load_stage(1, 1);

    int bufc = 0;
    for (int i = 0; i < NS; i++) {
        cp_wait<1>();
        __syncthreads();
        if (i + 2 < NS) {
            int nb = bufc + 2; if (nb >= NSTAGE) nb -= NSTAGE;
            load_stage(i + 2, nb);
        }

        const float* As = smem + bufc * (STAGE_B / 4);
        const float* Bs = As + (A_STAGE_B / 4);

#pragma unroll
        for (int ks = 0; ks < 4; ks++) {
            uint4 a4[4];
            uint2 b2[8];
#pragma unroll
            for (int mf = 0; mf < 4; mf++)
                a4[mf] = *(const uint4*)(As + (((ks * 2 + mw) * 4 + mf) * 32 + lane) * 4);
#pragma unroll
            for (int nf = 0; nf < 8; nf++)
                b2[nf] = *(const uint2*)(Bs + ((((ks * 4 + nw) * 8 + nf) * 32) + lane) * 2);
#pragma unroll
            for (int mf = 0; mf < 4; mf++)
#pragma unroll
                for (int nf = 0; nf < 8; nf++)
                    mma8(acc[mf][nf], (const uint32_t*)&a4[mf], (const uint32_t*)&b2[nf]);
        }
        bufc = (bufc + 1 == NSTAGE) ? 0 : bufc + 1;
    }

    // ---- epilogue ----
    const int p0 = pt * 256;
#pragma unroll
    for (int mf = 0; mf < 4; mf++) {
        const int coA = ct * 128 + mw * 64 + mf * 16 + lr;
        const int coB = coA + 8;
        const float scA = g_demod[b * C_OUT + coA] * CONV_SCALE;
        const float scB = g_demod[b * C_OUT + coB] * CONV_SCALE;
        float* opA = out + ((size_t)b * C_OUT + coA) * HW_ + p0;
        float* opB = out + ((size_t)b * C_OUT + coB) * HW_ + p0;
#pragma unroll
        for (int nf = 0; nf < 8; nf++) {
            const int px = nw * 64 + nf * 8 + lc * 2;
            float2 vA, vB;
            vA.x = acc[mf][nf][0] * scA; vA.y = acc[mf][nf][1] * scA;
            vB.x = acc[mf][nf][2] * scB; vB.y = acc[mf][nf][3] * scB;
            *(float2*)(opA + px) = vA;
            *(float2*)(opB + px) = vB;
        }
    }
}

// ---------------------------------------------------------------------------
extern "C" void kernel_launch(void* const* d_in, const int* in_sizes, int n_in,
                              void* d_out, int out_size) {
    const float* input = (const float*)d_in[0];
    const float* style = (const float*)d_in[1];
    const float* convw = (const float*)d_in[2];
    const float* modw  = (const float*)d_in[3];
    const float* modb  = (const float*)d_in[4];
    float* out = (float*)d_out;

    static int init_done = 0;
    if (!init_done) {
        cudaFuncSetAttribute(gemm_kernel, cudaFuncAttributeMaxDynamicSharedMemorySize, DYN_SMEM);
        init_done = 1;
    }

    style_kernel<<<B_, STYLE_D>>>(style, modw, modb);
    wsq_kernel<<<(C_OUT * C_IN + 511) / 512, 512>>>(convw);
    demod_kernel<<<B_, C_OUT>>>();
    apack_kernel<<<2304, 256>>>(convw);
    im2col_kernel<<<dim3(16, 64, B_), 256>>>(input);
    gemm_kernel<<<dim3(4, 16, 16), 256, DYN_SMEM>>>(out);
}

// round 13
// speedup vs baseline: 1.4282x; 1.0025x over previous
#include <cuda_runtime.h>
#include <cstdint>
#include <math.h>

#define B_      16
#define C_IN    512
#define C_OUT   512
#define HW_     4096
#define K_TOT   4608
#define STYLE_D 512

#define MOD_SCALE  0.04419417382415922f
#define CONV_SCALE 0.014731391274719738f
#define EPS_       1e-8f

// ---------------- device scratch ----------------
__device__ float g_s[B_ * C_IN];
__device__ float g_wsq[C_OUT * C_IN];
__device__ float g_demod[B_ * C_OUT];
// A_perm: [ct 4][s 144][4096 floats]  (fragment-ordered, tf32-rounded)
__device__ float g_A[(size_t)4 * 144 * 4096];
// X_perm: [b 16][pt 16][s 144][8192 floats] (fragment-ordered, tf32-rounded)
__device__ float g_X[(size_t)B_ * 16 * 144 * 8192];

// ---------------- helpers ----------------
__device__ __forceinline__ float to_tf32(float v) {
    asm("cvt.rna.tf32.f32 %0, %0;" : "+f"(v));
    return v;
}
__device__ __forceinline__ uint32_t s2u(const void* p) {
    uint32_t a;
    asm("{ .reg .u64 t; cvta.to.shared.u64 t, %1; cvt.u32.u64 %0, t; }" : "=r"(a) : "l"(p));
    return a;
}
__device__ __forceinline__ void cp16(uint32_t dst, const void* src) {
    asm volatile("cp.async.cg.shared.global [%0], [%1], 16;" :: "r"(dst), "l"(src));
}
__device__ __forceinline__ void cp_commit() {
    asm volatile("cp.async.commit_group;");
}
template <int N>
__device__ __forceinline__ void cp_wait() {
    asm volatile("cp.async.wait_group %0;" :: "n"(N));
}
__device__ __forceinline__ void mma8(float* d, const uint32_t* a, const uint32_t* b) {
    asm volatile(
        "mma.sync.aligned.m16n8k8.row.col.f32.tf32.tf32.f32 "
        "{%0,%1,%2,%3}, {%4,%5,%6,%7}, {%8,%9}, {%0,%1,%2,%3};"
        : "+f"(d[0]), "+f"(d[1]), "+f"(d[2]), "+f"(d[3])
        : "r"(a[0]), "r"(a[1]), "r"(a[2]), "r"(a[3]), "r"(b[0]), "r"(b[1]));
}

// ---------------------------------------------------------------------------
// K0: s[b,ci]
// ---------------------------------------------------------------------------
__global__ void style_kernel(const float* __restrict__ style,
                             const float* __restrict__ modw,
                             const float* __restrict__ modb) {
    int b = blockIdx.x, ci = threadIdx.x;
    __shared__ float st[STYLE_D];
    st[ci] = style[b * STYLE_D + ci];
    __syncthreads();
    const float* wr = modw + (size_t)ci * STYLE_D;
    float acc = 0.f;
#pragma unroll 8
    for (int d = 0; d < STYLE_D; d++) acc += st[d] * wr[d];
    g_s[b * C_IN + ci] = acc * MOD_SCALE + modb[ci];
}

// ---------------------------------------------------------------------------
// K1: wsq[co,ci] = sum_k W^2
// ---------------------------------------------------------------------------
__global__ void wsq_kernel(const float* __restrict__ w) {
    int i = blockIdx.x * blockDim.x + threadIdx.x;
    if (i < C_OUT * C_IN) {
        const float* p = w + (size_t)i * 9;
        float a = 0.f;
#pragma unroll
        for (int k = 0; k < 9; k++) a += p[k] * p[k];
        g_wsq[i] = a;
    }
}

// ---------------------------------------------------------------------------
// K2: demod[b,co]
// ---------------------------------------------------------------------------
__global__ void demod_kernel() {
    int b = blockIdx.x, co = threadIdx.x;
    __shared__ float s2[C_IN];
    float sv = g_s[b * C_IN + co];
    s2[co] = sv * sv;
    __syncthreads();
    const float* q = g_wsq + (size_t)co * C_IN;
    float a = 0.f;
#pragma unroll 8
    for (int ci = 0; ci < C_IN; ci++) a += s2[ci] * q[ci];
    g_demod[b * C_OUT + co] = rsqrtf(a * (CONV_SCALE * CONV_SCALE) + EPS_);
}

// ---------------------------------------------------------------------------
// K3: A_perm. block of 4096 floats per (ct,s): [ks 4][mh 2][mf 4][lane 32][e 4]
// ---------------------------------------------------------------------------
__global__ void apack_kernel(const float* __restrict__ w) {
    size_t idx = ((size_t)blockIdx.x * 256 + threadIdx.x) * 4;
    int within = (int)(idx & 4095);
    int blkid  = (int)(idx >> 12);
    int s  = blkid % 144;
    int ct = blkid / 144;
    int lane = (within >> 2) & 31;
    int mf   = (within >> 7) & 3;
    int mh   = (within >> 9) & 1;
    int ks   = within >> 10;
    int lr = lane >> 2, lc = lane & 3;
    float4 v;
#pragma unroll
    for (int e = 0; e < 4; e++) {
        int kc  = ks * 8 + lc + (e >> 1) * 4;
        int row = mh * 64 + mf * 16 + lr + (e & 1) * 8;
        int co  = ct * 128 + row;
        int K   = s * 32 + kc;
        int k = K >> 9, ci = K & 511;
        ((float*)&v)[e] = to_tf32(w[((size_t)co * 512 + ci) * 9 + k]);
    }
    *(float4*)&g_A[idx] = v;
}

// ---------------------------------------------------------------------------
// K4: im2col -> X_perm, GATHER form (coalesced stores).
// block = (ci0 group 32, y row, b). stage s = k*16 + ci0/32; pt=y>>2; nw=y&3.
// Per k this CTA owns the 2048 floats [ks 4][nw fixed][nf 8][le 64] of the
// (b,pt,s) 8192-float block. Thread t writes 8 consecutive floats:
//   run = t>>3 -> ks=run>>3, nf=run&7 ; off=(t&7)*8 ; le=off+j
//   lane=le>>1, e=le&1, lr=lane>>2, lc=lane&3
//   ci = ks*8 + e*4 + lc ; x = nf*8 + lr ; src = In3[ci][kh][x+kw]
// ---------------------------------------------------------------------------
__global__ __launch_bounds__(256) void im2col_kernel(const float* __restrict__ input) {
    const int ci0 = blockIdx.x * 32;
    const int y   = blockIdx.y;
    const int b   = blockIdx.z;
    const int t   = threadIdx.x;
    __shared__ float In3[32][3][68];
    __shared__ float sS[32];
    if (t < 32) sS[t] = g_s[b * C_IN + ci0 + t];
    __syncthreads();
    for (int idx = t; idx < 32 * 3 * 66; idx += 256) {
        int ci = idx / 198, r = idx % 198, dy = r / 66, xx = r % 66;
        int ys = y + dy - 1, xs = xx - 1;
        float v = 0.f;
        if ((unsigned)ys < 64 && (unsigned)xs < 64)
            v = input[(((size_t)b * C_IN + ci0 + ci) * 64 + ys) * 64 + xs] * sS[ci];
        In3[ci][dy][xx] = to_tf32(v);
    }
    __syncthreads();

    const int pt = y >> 2;
    const int nw = y & 3;
    const int run = t >> 3;          // 0..31
    const int ks  = run >> 3;        // 0..3
    const int nf  = run & 7;         // 0..7
    const int off = (t & 7) * 8;     // 0..56

    // decode the 8 source coordinates once (k-independent)
    int sci[8], sx[8];
#pragma unroll
    for (int j = 0; j < 8; j++) {
        int le = off + j;
        int lane = le >> 1, e = le & 1;
        int lr = lane >> 2, lc = lane & 3;
        sci[j] = ks * 8 + e * 4 + lc;
        sx[j]  = nf * 8 + lr;
    }
    const int dst_off = ((ks * 4 + nw) * 8 + nf) * 64 + off;

#pragma unroll
    for (int k = 0; k < 9; k++) {
        const int kh = k / 3, kw = k % 3;
        float* base = g_X + (((size_t)(b * 16 + pt) * 144) + k * 16 + (ci0 >> 5)) * 8192;
        float v[8];
#pragma unroll
        for (int j = 0; j < 8; j++) v[j] = In3[sci[j]][kh][sx[j] + kw];
        *(float4*)&base[dst_off]     = make_float4(v[0], v[1], v[2], v[3]);
        *(float4*)&base[dst_off + 4] = make_float4(v[4], v[5], v[6], v[7]);
    }
}

// ---------------------------------------------------------------------------
// K5: GEMM tf32 (unchanged from 2071us run). CTA: M=128 x N=256, 8 warps
// (2Mx4N), warp 64x64, K=4608 in 144 stages of 32, 3-stage cp.async ring.
// ---------------------------------------------------------------------------
#define A_STAGE_B 16384
#define B_STAGE_B 32768
#define STAGE_B   (A_STAGE_B + B_STAGE_B)   // 49152
#define NSTAGE    3
#define NS        144
#define DYN_SMEM  (NSTAGE * STAGE_B)        // 147456

__global__ __launch_bounds__(256, 1) void gemm_kernel(float* __restrict__ out) {
    extern __shared__ float smem[];
    const uint32_t sb = s2u(smem);
    const int t = threadIdx.x;
    const int w = t >> 5, lane = t & 31;
    const int mw = w >> 2;
    const int nw = w & 3;
    const int lr = lane >> 2;
    const int lc = lane & 3;

    const int ct = blockIdx.x;
    const int pt = blockIdx.y;
    const int b  = blockIdx.z;

    const float* Ab = g_A + (size_t)ct * 144 * 4096;
    const float* Xb = g_X + ((size_t)(b * 16 + pt) * 144) * 8192;

    auto load_stage = [&](int stage, int buf) {
        const uint32_t base = sb + buf * STAGE_B;
        const float* as = Ab + (size_t)stage * 4096;
        const float* xs = Xb + (size_t)stage * 8192;
#pragma unroll
        for (int j = 0; j < 4; j++) {
            int c = j * 256 + t;
            cp16(base + c * 16, as + c * 4);
        }
#pragma unroll
        for (int j = 0; j < 8; j++) {
            int c = j * 256 + t;
            cp16(base + A_STAGE_B + c * 16, xs + c * 4);
        }
        cp_commit();
    };

    float acc[4][8][4];
#pragma unroll
    for (int i = 0; i < 4; i++)
#pragma unroll
        for (int j = 0; j < 8; j++)
#pragma unroll
            for (int c = 0; c < 4; c++) acc[i][j][c] = 0.f;

    load_stage(0, 0);
    load_stage(1, 1);

    int bufc = 0;
    for (int i = 0; i < NS; i++) {
        cp_wait<1>();
        __syncthreads();
        if (i + 2 < NS) {
            int nb = bufc + 2; if (nb >= NSTAGE) nb -= NSTAGE;
            load_stage(i + 2, nb);
        }

        const float* As = smem + bufc * (STAGE_B / 4);
        const float* Bs = As + (A_STAGE_B / 4);

#pragma unroll
        for (int ks = 0; ks < 4; ks++) {
            uint4 a4[4];
            uint2 b2[8];
#pragma unroll
            for (int mf = 0; mf < 4; mf++)
                a4[mf] = *(const uint4*)(As + (((ks * 2 + mw) * 4 + mf) * 32 + lane) * 4);
#pragma unroll
            for (int nf = 0; nf < 8; nf++)
                b2[nf] = *(const uint2*)(Bs + ((((ks * 4 + nw) * 8 + nf) * 32) + lane) * 2);
#pragma unroll
            for (int mf = 0; mf < 4; mf++)
#pragma unroll
                for (int nf = 0; nf < 8; nf++)
                    mma8(acc[mf][nf], (const uint32_t*)&a4[mf], (const uint32_t*)&b2[nf]);
        }
        bufc = (bufc + 1 == NSTAGE) ? 0 : bufc + 1;
    }

    // ---- epilogue ----
    const int p0 = pt * 256;
#pragma unroll
    for (int mf = 0; mf < 4; mf++) {
        const int coA = ct * 128 + mw * 64 + mf * 16 + lr;
        const int coB = coA + 8;
        const float scA = g_demod[b * C_OUT + coA] * CONV_SCALE;
        const float scB = g_demod[b * C_OUT + coB] * CONV_SCALE;
        float* opA = out + ((size_t)b * C_OUT + coA) * HW_ + p0;
        float* opB = out + ((size_t)b * C_OUT + coB) * HW_ + p0;
#pragma unroll
        for (int nf = 0; nf < 8; nf++) {
            const int px = nw * 64 + nf * 8 + lc * 2;
            float2 vA, vB;
            vA.x = acc[mf][nf][0] * scA; vA.y = acc[mf][nf][1] * scA;
            vB.x = acc[mf][nf][2] * scB; vB.y = acc[mf][nf][3] * scB;
            *(float2*)(opA + px) = vA;
            *(float2*)(opB + px) = vB;
        }
    }
}

// ---------------------------------------------------------------------------
extern "C" void kernel_launch(void* const* d_in, const int* in_sizes, int n_in,
                              void* d_out, int out_size) {
    const float* input = (const float*)d_in[0];
    const float* style = (const float*)d_in[1];
    const float* convw = (const float*)d_in[2];
    const float* modw  = (const float*)d_in[3];
    const float* modb  = (const float*)d_in[4];
    float* out = (float*)d_out;

    static int init_done = 0;
    if (!init_done) {
        cudaFuncSetAttribute(gemm_kernel, cudaFuncAttributeMaxDynamicSharedMemorySize, DYN_SMEM);
        init_done = 1;
    }

    style_kernel<<<B_, STYLE_D>>>(style, modw, modb);
    wsq_kernel<<<(C_OUT * C_IN + 511) / 512, 512>>>(convw);
    demod_kernel<<<B_, C_OUT>>>();
    apack_kernel<<<2304, 256>>>(convw);
    im2col_kernel<<<dim3(16, 64, B_), 256>>>(input);
    gemm_kernel<<<dim3(4, 16, 16), 256, DYN_SMEM>>>(out);
}

// round 15
// speedup vs baseline: 2.0286x; 1.4205x over previous
#include <cuda_runtime.h>
#include <cstdint>
#include <math.h>

#define B_      16
#define C_IN    512
#define C_OUT   512
#define HW_     4096
#define NTOT    16384          // B_*1024 tiles
#define STYLE_D 512

#define MOD_SCALE  0.04419417382415922f
#define CONV_SCALE 0.014731391274719738f
#define EPS_       1e-8f

// ---------------- device scratch ----------------
__device__ float g_s[B_ * C_IN];
__device__ float g_wsq[C_OUT * C_IN];
__device__ float g_demod[B_ * C_OUT];
// U: [xinu 16][ct 4][s 16][4096]  fragment-ordered tf32 (16.8 MB)
__device__ float g_U[(size_t)16 * 4 * 16 * 4096];
// V: [xinu 16][nt 64][s 16][8192] fragment-ordered tf32 (512 MB)
__device__ float g_V[(size_t)16 * 64 * 16 * 8192];
// M: [xinu 16][co 512][n 16384]  fp32 GEMM results (512 MB)
__device__ float g_M[(size_t)16 * C_OUT * NTOT];

// ---------------- helpers ----------------
__device__ __forceinline__ float to_tf32(float v) {
    asm("cvt.rna.tf32.f32 %0, %0;" : "+f"(v));
    return v;
}
__device__ __forceinline__ uint32_t s2u(const void* p) {
    uint32_t a;
    asm("{ .reg .u64 t; cvta.to.shared.u64 t, %1; cvt.u32.u64 %0, t; }" : "=r"(a) : "l"(p));
    return a;
}
__device__ __forceinline__ void cp16(uint32_t dst, const void* src) {
    asm volatile("cp.async.cg.shared.global [%0], [%1], 16;" :: "r"(dst), "l"(src));
}
__device__ __forceinline__ void cp_commit() {
    asm volatile("cp.async.commit_group;");
}
template <int N>
__device__ __forceinline__ void cp_wait() {
    asm volatile("cp.async.wait_group %0;" :: "n"(N));
}
__device__ __forceinline__ void mma8(float* d, const uint32_t* a, const uint32_t* b) {
    asm volatile(
        "mma.sync.aligned.m16n8k8.row.col.f32.tf32.tf32.f32 "
        "{%0,%1,%2,%3}, {%4,%5,%6,%7}, {%8,%9}, {%0,%1,%2,%3};"
        : "+f"(d[0]), "+f"(d[1]), "+f"(d[2]), "+f"(d[3])
        : "r"(a[0]), "r"(a[1]), "r"(a[2]), "r"(a[3]), "r"(b[0]), "r"(b[1]));
}

// ---------------------------------------------------------------------------
// K0: s[b,ci]
// ---------------------------------------------------------------------------
__global__ void style_kernel(const float* __restrict__ style,
                             const float* __restrict__ modw,
                             const float* __restrict__ modb) {
    int b = blockIdx.x, ci = threadIdx.x;
    __shared__ float st[STYLE_D];
    st[ci] = style[b * STYLE_D + ci];
    __syncthreads();
    const float* wr = modw + (size_t)ci * STYLE_D;
    float acc = 0.f;
#pragma unroll 8
    for (int d = 0; d < STYLE_D; d++) acc += st[d] * wr[d];
    g_s[b * C_IN + ci] = acc * MOD_SCALE + modb[ci];
}

// ---------------------------------------------------------------------------
// K1: wsq[co,ci] = sum_k W^2
// ---------------------------------------------------------------------------
__global__ void wsq_kernel(const float* __restrict__ w) {
    int i = blockIdx.x * blockDim.x + threadIdx.x;
    if (i < C_OUT * C_IN) {
        const float* p = w + (size_t)i * 9;
        float a = 0.f;
#pragma unroll
        for (int k = 0; k < 9; k++) a += p[k] * p[k];
        g_wsq[i] = a;
    }
}

// ---------------------------------------------------------------------------
// K2: demod[b,co]
// ---------------------------------------------------------------------------
__global__ void demod_kernel() {
    int b = blockIdx.x, co = threadIdx.x;
    __shared__ float s2[C_IN];
    float sv = g_s[b * C_IN + co];
    s2[co] = sv * sv;
    __syncthreads();
    const float* q = g_wsq + (size_t)co * C_IN;
    float a = 0.f;
#pragma unroll 8
    for (int ci = 0; ci < C_IN; ci++) a += s2[ci] * q[ci];
    g_demod[b * C_OUT + co] = rsqrtf(a * (CONV_SCALE * CONV_SCALE) + EPS_);
}

// ---------------------------------------------------------------------------
// K3: weight transform U = G g G^T, fragment-ordered.
// Block of 4096 floats per (xinu,ct,s): [ks 4][mh 2][mf 4][lane 32][e 4]
// ---------------------------------------------------------------------------
__global__ void wino_w_kernel(const float* __restrict__ w) {
    const float Gr[4][3] = {{1.f, 0.f, 0.f}, {0.5f, 0.5f, 0.5f},
                            {0.5f, -0.5f, 0.5f}, {0.f, 0.f, 1.f}};
    size_t idx = ((size_t)blockIdx.x * 256 + threadIdx.x) * 4;
    int within = (int)(idx & 4095);
    int blk = (int)(idx >> 12);
    int s = blk & 15, ct = (blk >> 4) & 3, xinu = blk >> 6;
    int xi = xinu >> 2, nu = xinu & 3;
    int lane = (within >> 2) & 31;
    int mf = (within >> 7) & 3;
    int mh = (within >> 9) & 1;
    int ks = within >> 10;
    int lr = lane >> 2, lc = lane & 3;
    float4 vout;
#pragma unroll
    for (int e = 0; e < 4; e++) {
        int kc = ks * 8 + lc + (e >> 1) * 4;
        int ci = s * 32 + kc;
        int co = ct * 128 + mh * 64 + mf * 16 + lr + (e & 1) * 8;
        const float* g = w + ((size_t)co * 512 + ci) * 9;
        float u = 0.f;
#pragma unroll
        for (int a = 0; a < 3; a++)
#pragma unroll
            for (int c = 0; c < 3; c++)
                u += Gr[xi][a] * Gr[nu][c] * g[a * 3 + c];
        ((float*)&vout)[e] = to_tf32(u);
    }
    *(float4*)&g_U[idx] = vout;
}

// ---------------------------------------------------------------------------
// K4: input transform V = B^T d B (d modulated by s), fragment-ordered.
// block = (cig 16, ty 32, b 16); covers 32 ci x 32 tx tiles x 16 xinu.
// ---------------------------------------------------------------------------
#define VIN_SMEM (32 * 4 * 66 * 4 + 8 * 32 * 33 * 4)   // 67584 B

__global__ __launch_bounds__(256) void wino_in_kernel(const float* __restrict__ input) {
    extern __shared__ float sm[];
    float* sIn = sm;                    // [32][4][66]
    float* sV  = sm + 32 * 4 * 66;      // [8][32][33]
    __shared__ float sS[32];

    const int cig = blockIdx.x;
    const int ty  = blockIdx.y;
    const int b   = blockIdx.z;
    const int ci0 = cig * 32;
    const int t   = threadIdx.x;

    if (t < 32) sS[t] = g_s[b * C_IN + ci0 + t];
    __syncthreads();

    for (int idx = t; idx < 32 * 4 * 66; idx += 256) {
        int ci = idx / 264, r = idx % 264, i = r / 66, xx = r % 66;
        int ys = 2 * ty - 1 + i, xs = xx - 1;
        float v = 0.f;
        if ((unsigned)ys < 64 && (unsigned)xs < 64)
            v = input[(((size_t)b * C_IN + ci0 + ci) * 64 + ys) * 64 + xs] * sS[ci];
        sIn[idx] = v;
    }
    __syncthreads();

    const int nt     = b * 4 + (ty >> 3);
    const int nw     = (ty & 7) >> 1;
    const int nfbase = (ty & 1) * 4;
    const int run = t >> 4;          // 0..15
    const int ks  = run >> 2;
    const int nfl = run & 3;
    const int off = (t & 15) * 4;

    for (int p = 0; p < 2; p++) {
        // ---- compute pass: all (ci,tx), store xinu in [p*8, p*8+8) ----
#pragma unroll
        for (int q = 0; q < 4; q++) {
            int pair = q * 256 + t;
            int ci = pair >> 5, tx = pair & 31;
            const float* dp = sIn + ci * 264 + 2 * tx;
            float z[4][4];
#pragma unroll
            for (int j = 0; j < 4; j++) {
                float d0 = dp[0 * 66 + j], d1 = dp[1 * 66 + j];
                float d2 = dp[2 * 66 + j], d3 = dp[3 * 66 + j];
                z[0][j] = d0 - d2; z[1][j] = d1 + d2;
                z[2][j] = d2 - d1; z[3][j] = d1 - d3;
            }
#pragma unroll
            for (int i = 0; i < 4; i++) {
                float vv[4];
                vv[0] = z[i][0] - z[i][2];
                vv[1] = z[i][1] + z[i][2];
                vv[2] = z[i][2] - z[i][1];
                vv[3] = z[i][1] - z[i][3];
#pragma unroll
                for (int j = 0; j < 4; j++) {
                    int xl = i * 4 + j - p * 8;
                    if (xl >= 0 && xl < 8)
                        sV[(xl * 32 + ci) * 33 + tx] = vv[j];
                }
            }
        }
        __syncthreads();
        // ---- gather-write pass (coalesced float4 stores) ----
#pragma unroll
        for (int xl = 0; xl < 8; xl++) {
            int xinu = p * 8 + xl;
            float* base = g_V + (((size_t)xinu * 64 + nt) * 16 + cig) * 8192;
            float v[4];
#pragma unroll
            for (int j = 0; j < 4; j++) {
                int le = off + j;
                int lane = le >> 1, e = le & 1;
                int lr = lane >> 2, lc = lane & 3;
                int kc = ks * 8 + e * 4 + lc;
                int tx = nfl * 8 + lr;
                v[j] = to_tf32(sV[(xl * 32 + kc) * 33 + tx]);
            }
            int nf = nfbase + nfl;
            int fidx = ((ks * 4 + nw) * 8 + nf) * 64 + off;
            *(float4*)&base[fidx] = make_float4(v[0], v[1], v[2], v[3]);
        }
        __syncthreads();
    }
}

// ---------------------------------------------------------------------------
// K5: 16 batched GEMMs (one per xinu): M[xinu][co][n] = sum_ci U*V.
// CTA: 128 co x 256 n, 8 warps (2Mx4N), warp 64x64, K=512 in 16 stages of 32.
// 3-stage cp.async ring, fragment-ordered smem. grid (4 ct, 64 nt, 16 xinu).
// ---------------------------------------------------------------------------
#define A_STAGE_B 16384
#define B_STAGE_B 32768
#define STAGE_B   (A_STAGE_B + B_STAGE_B)
#define NSTAGE    3
#define NS        16
#define DYN_SMEM  (NSTAGE * STAGE_B)        // 147456

__global__ __launch_bounds__(256, 1) void gemm_kernel() {
    extern __shared__ float smem[];
    const uint32_t sb = s2u(smem);
    const int t = threadIdx.x;
    const int w = t >> 5, lane = t & 31;
    const int mw = w >> 2;
    const int nw = w & 3;
    const int lr = lane >> 2;
    const int lc = lane & 3;

    const int ct   = blockIdx.x;
    const int nt   = blockIdx.y;
    const int xinu = blockIdx.z;

    const float* Ab = g_U + ((size_t)xinu * 4 + ct) * 16 * 4096;
    const float* Xb = g_V + ((size_t)xinu * 64 + nt) * 16 * 8192;

    // FIXED loader: A = 1024 cp16 chunks (4 x 256), B = 2048 chunks (8 x 256)
    auto load_stage = [&](int stage, int buf) {
        const uint32_t base = sb + buf * STAGE_B;
        const float* as = Ab + (size_t)stage * 4096;
        const float* xs = Xb + (size_t)stage * 8192;
#pragma unroll
        for (int j = 0; j < 4; j++) {
            int c = j * 256 + t;
            cp16(base + c * 16, as + c * 4);
        }
#pragma unroll
        for (int j = 0; j < 8; j++) {
            int c = j * 256 + t;
            cp16(base + A_STAGE_B + c * 16, xs + c * 4);
        }
        cp_commit();
    };

    float acc[4][8][4];
#pragma unroll
    for (int i = 0; i < 4; i++)
#pragma unroll
        for (int j = 0; j < 8; j++)
#pragma unroll
            for (int c = 0; c < 4; c++) acc[i][j][c] = 0.f;

    load_stage(0, 0);
    load_stage(1, 1);

    int bufc = 0;
    for (int i = 0; i < NS; i++) {
        cp_wait<1>();
        __syncthreads();
        if (i + 2 < NS) {
            int nb = bufc + 2; if (nb >= NSTAGE) nb -= NSTAGE;
            load_stage(i + 2, nb);
        }

        const float* As = smem + bufc * (STAGE_B / 4);
        const float* Bs = As + (A_STAGE_B / 4);

#pragma unroll
        for (int ks = 0; ks < 4; ks++) {
            uint4 a4[4];
            uint2 b2[8];
#pragma unroll
            for (int mf = 0; mf < 4; mf++)
                a4[mf] = *(const uint4*)(As + (((ks * 2 + mw) * 4 + mf) * 32 + lane) * 4);
#pragma unroll
            for (int nf = 0; nf < 8; nf++)
                b2[nf] = *(const uint2*)(Bs + ((((ks * 4 + nw) * 8 + nf) * 32) + lane) * 2);
#pragma unroll
            for (int mf = 0; mf < 4; mf++)
#pragma unroll
                for (int nf = 0; nf < 8; nf++)
                    mma8(acc[mf][nf], (const uint32_t*)&a4[mf], (const uint32_t*)&b2[nf]);
        }
        bufc = (bufc + 1 == NSTAGE) ? 0 : bufc + 1;
    }

    // ---- epilogue: raw M (no demod yet) ----
    const size_t n0 = (size_t)nt * 256;
#pragma unroll
    for (int mf = 0; mf < 4; mf++) {
        const int coA = ct * 128 + mw * 64 + mf * 16 + lr;
        const int coB = coA + 8;
        float* opA = g_M + ((size_t)xinu * C_OUT + coA) * NTOT + n0;
        float* opB = g_M + ((size_t)xinu * C_OUT + coB) * NTOT + n0;
#pragma unroll
        for (int nf = 0; nf < 8; nf++) {
            const int px = nw * 64 + nf * 8 + lc * 2;
            float2 vA, vB;
            vA.x = acc[mf][nf][0]; vA.y = acc[mf][nf][1];
            vB.x = acc[mf][nf][2]; vB.y = acc[mf][nf][3];
            *(float2*)(opA + px) = vA;
            *(float2*)(opB + px) = vB;
        }
    }
}

// ---------------------------------------------------------------------------
// K6: output transform Y = A^T M A, scaled by demod*CONV_SCALE.
// grid (co 512, b 16), block 256: thread t -> ty=t>>3, tx0=(t&7)*4 (4 tiles).
// ---------------------------------------------------------------------------
__global__ __launch_bounds__(256) void wino_out_kernel(float* __restrict__ out) {
    const int co = blockIdx.x, b = blockIdx.y;
    const int t = threadIdx.x;
    const int ty = t >> 3, tx0 = (t & 7) * 4;
    const size_t nbase = (size_t)b * 1024 + ty * 32 + tx0;

    float4 m[16];
#pragma unroll
    for (int xinu = 0; xinu < 16; xinu++)
        m[xinu] = *(const float4*)&g_M[((size_t)xinu * C_OUT + co) * NTOT + nbase];

    const float sc = g_demod[b * C_OUT + co] * CONV_SCALE;
    float r0[8], r1[8];
#pragma unroll
    for (int q = 0; q < 4; q++) {
        float z0[4], z1[4];
#pragma unroll
        for (int nu = 0; nu < 4; nu++) {
            float m0 = ((const float*)&m[0 * 4 + nu])[q];
            float m1 = ((const float*)&m[1 * 4 + nu])[q];
            float m2 = ((const float*)&m[2 * 4 + nu])[q];
            float m3 = ((const float*)&m[3 * 4 + nu])[q];
            z0[nu] = m0 + m1 + m2;
            z1[nu] = m1 - m2 - m3;
        }
        r0[q * 2 + 0] = (z0[0] + z0[1] + z0[2]) * sc;
        r0[q * 2 + 1] = (z0[1] - z0[2] - z0[3]) * sc;
        r1[q * 2 + 0] = (z1[0] + z1[1] + z1[2]) * sc;
        r1[q * 2 + 1] = (z1[1] - z1[2] - z1[3]) * sc;
    }

    float* op = out + (((size_t)b * C_OUT + co) * 64 + 2 * ty) * 64 + 2 * tx0;
    *(float4*)(op)      = make_float4(r0[0], r0[1], r0[2], r0[3]);
    *(float4*)(op + 4)  = make_float4(r0[4], r0[5], r0[6], r0[7]);
    *(float4*)(op + 64) = make_float4(r1[0], r1[1], r1[2], r1[3]);
    *(float4*)(op + 68) = make_float4(r1[4], r1[5], r1[6], r1[7]);
}

// ---------------------------------------------------------------------------
extern "C" void kernel_launch(void* const* d_in, const int* in_sizes, int n_in,
                              void* d_out, int out_size) {
    const float* input = (const float*)d_in[0];
    const float* style = (const float*)d_in[1];
    const float* convw = (const float*)d_in[2];
    const float* modw  = (const float*)d_in[3];
    const float* modb  = (const float*)d_in[4];
    float* out = (float*)d_out;

    static int init_done = 0;
    if (!init_done) {
        cudaFuncSetAttribute(gemm_kernel, cudaFuncAttributeMaxDynamicSharedMemorySize, DYN_SMEM);
        cudaFuncSetAttribute(wino_in_kernel, cudaFuncAttributeMaxDynamicSharedMemorySize, VIN_SMEM);
        init_done = 1;
    }

    style_kernel<<<B_, STYLE_D>>>(style, modw, modb);
    wsq_kernel<<<(C_OUT * C_IN + 511) / 512, 512>>>(convw);
    demod_kernel<<<B_, C_OUT>>>();
    wino_w_kernel<<<4096, 256>>>(convw);
    wino_in_kernel<<<dim3(16, 32, 16), 256, VIN_SMEM>>>(input);
    gemm_kernel<<<dim3(4, 64, 16), 256, DYN_SMEM>>>();
    wino_out_kernel<<<dim3(C_OUT, B_), 256>>>(out);
}

// round 16
// speedup vs baseline: 2.1433x; 1.0565x over previous
#include <cuda_runtime.h>
#include <cstdint>
#include <math.h>

#define B_      16
#define C_IN    512
#define C_OUT   512
#define HW_     4096
#define NTOT    16384          // B_*1024 tiles
#define STYLE_D 512

#define MOD_SCALE  0.04419417382415922f
#define CONV_SCALE 0.014731391274719738f
#define EPS_       1e-8f

// ---------------- device scratch ----------------
__device__ float g_s[B_ * C_IN];
__device__ float g_wsq[C_OUT * C_IN];
__device__ float g_demod[B_ * C_OUT];
// U: [xinu 16][ct 4][s 16][4096]  fragment-ordered tf32 (16.8 MB)
__device__ float g_U[(size_t)16 * 4 * 16 * 4096];
// V: [xinu 16][nt 128][s 16][4096] fragment-ordered tf32 (512 MB)
__device__ float g_V[(size_t)16 * 128 * 16 * 4096];
// M: [xinu 16][co 512][n 16384]  fp32 GEMM results (512 MB)
__device__ float g_M[(size_t)16 * C_OUT * NTOT];

// ---------------- helpers ----------------
__device__ __forceinline__ float to_tf32(float v) {
    asm("cvt.rna.tf32.f32 %0, %0;" : "+f"(v));
    return v;
}
__device__ __forceinline__ uint32_t s2u(const void* p) {
    uint32_t a;
    asm("{ .reg .u64 t; cvta.to.shared.u64 t, %1; cvt.u32.u64 %0, t; }" : "=r"(a) : "l"(p));
    return a;
}
__device__ __forceinline__ void cp16(uint32_t dst, const void* src) {
    asm volatile("cp.async.cg.shared.global [%0], [%1], 16;" :: "r"(dst), "l"(src));
}
__device__ __forceinline__ void cp_commit() {
    asm volatile("cp.async.commit_group;");
}
template <int N>
__device__ __forceinline__ void cp_wait() {
    asm volatile("cp.async.wait_group %0;" :: "n"(N));
}
__device__ __forceinline__ void mma8(float* d, const uint32_t* a, const uint32_t* b) {
    asm volatile(
        "mma.sync.aligned.m16n8k8.row.col.f32.tf32.tf32.f32 "
        "{%0,%1,%2,%3}, {%4,%5,%6,%7}, {%8,%9}, {%0,%1,%2,%3};"
        : "+f"(d[0]), "+f"(d[1]), "+f"(d[2]), "+f"(d[3])
        : "r"(a[0]), "r"(a[1]), "r"(a[2]), "r"(a[3]), "r"(b[0]), "r"(b[1]));
}

// ---------------------------------------------------------------------------
// K0: s[b,ci]
// ---------------------------------------------------------------------------
__global__ void style_kernel(const float* __restrict__ style,
                             const float* __restrict__ modw,
                             const float* __restrict__ modb) {
    int b = blockIdx.x, ci = threadIdx.x;
    __shared__ float st[STYLE_D];
    st[ci] = style[b * STYLE_D + ci];
    __syncthreads();
    const float* wr = modw + (size_t)ci * STYLE_D;
    float acc = 0.f;
#pragma unroll 8
    for (int d = 0; d < STYLE_D; d++) acc += st[d] * wr[d];
    g_s[b * C_IN + ci] = acc * MOD_SCALE + modb[ci];
}

// ---------------------------------------------------------------------------
// K1: wsq[co,ci] = sum_k W^2
// ---------------------------------------------------------------------------
__global__ void wsq_kernel(const float* __restrict__ w) {
    int i = blockIdx.x * blockDim.x + threadIdx.x;
    if (i < C_OUT * C_IN) {
        const float* p = w + (size_t)i * 9;
        float a = 0.f;
#pragma unroll
        for (int k = 0; k < 9; k++) a += p[k] * p[k];
        g_wsq[i] = a;
    }
}

// ---------------------------------------------------------------------------
// K2: demod[b,co]
// ---------------------------------------------------------------------------
__global__ void demod_kernel() {
    int b = blockIdx.x, co = threadIdx.x;
    __shared__ float s2[C_IN];
    float sv = g_s[b * C_IN + co];
    s2[co] = sv * sv;
    __syncthreads();
    const float* q = g_wsq + (size_t)co * C_IN;
    float a = 0.f;
#pragma unroll 8
    for (int ci = 0; ci < C_IN; ci++) a += s2[ci] * q[ci];
    g_demod[b * C_OUT + co] = rsqrtf(a * (CONV_SCALE * CONV_SCALE) + EPS_);
}

// ---------------------------------------------------------------------------
// K3: weight transform U = G g G^T, ALL 16 xinu per weight read.
// Thread owns 4 (co,ci) pairs (one float4 slot of the [ct][s][4096] space),
// reads 4 g-vectors once, writes 16 xinu float4 blocks (stride 4*16*4096).
// grid 256, block 256.
// ---------------------------------------------------------------------------
__global__ void wino_w_kernel(const float* __restrict__ w) {
    size_t idx = ((size_t)blockIdx.x * 256 + threadIdx.x) * 4;
    int within = (int)(idx & 4095);
    int blk = (int)(idx >> 12);
    int s = blk & 15, ct = blk >> 4;
    int lane = (within >> 2) & 31;
    int mf = (within >> 7) & 3;
    int mh = (within >> 9) & 1;
    int ks = within >> 10;
    int lr = lane >> 2, lc = lane & 3;

    // Gg rows per element e: [4][3]
    float gg[4][4][3];   // [e][row xi][col c]
#pragma unroll
    for (int e = 0; e < 4; e++) {
        int kc = ks * 8 + lc + (e >> 1) * 4;
        int ci = s * 32 + kc;
        int co = ct * 128 + mh * 64 + mf * 16 + lr + (e & 1) * 8;
        const float* g = w + ((size_t)co * 512 + ci) * 9;
#pragma unroll
        for (int c = 0; c < 3; c++) {
            float g0 = g[0 * 3 + c], g1 = g[1 * 3 + c], g2 = g[2 * 3 + c];
            gg[e][0][c] = g0;
            gg[e][1][c] = 0.5f * (g0 + g1 + g2);
            gg[e][2][c] = 0.5f * (g0 - g1 + g2);
            gg[e][3][c] = g2;
        }
    }
#pragma unroll
    for (int xi = 0; xi < 4; xi++) {
#pragma unroll
        for (int nu = 0; nu < 4; nu++) {
            float4 vout;
#pragma unroll
            for (int e = 0; e < 4; e++) {
                float a0 = gg[e][xi][0], a1 = gg[e][xi][1], a2 = gg[e][xi][2];
                float u;
                if (nu == 0)      u = a0;
                else if (nu == 1) u = 0.5f * (a0 + a1 + a2);
                else if (nu == 2) u = 0.5f * (a0 - a1 + a2);
                else              u = a2;
                ((float*)&vout)[e] = to_tf32(u);
            }
            *(float4*)&g_U[(size_t)(xi * 4 + nu) * (4 * 16 * 4096) + idx] = vout;
        }
    }
}

// ---------------------------------------------------------------------------
// K4: input transform V = B^T d B, fragment-ordered for the N=128 B-block.
// block = (cig 16, ty 32, b 16): 32 ci x 32 tx tiles x 16 xinu.
// nt = b*8 + (ty>>2); nw = ty&3; per xl: 1024 floats
//   fidx = ((ks*4+nw)*4+nf)*64 + off, thread t: run=t>>4 (ks=run>>2, nf=run&3),
//   off=(t&15)*4; le=off+j: lane=le>>1, e=le&1; kc=ks*8+e*4+(lane&3); tx=nf*8+(lane>>2)
// ---------------------------------------------------------------------------
#define VIN_SMEM (32 * 4 * 66 * 4 + 8 * 32 * 33 * 4)   // 67584 B

__global__ __launch_bounds__(256) void wino_in_kernel(const float* __restrict__ input) {
    extern __shared__ float sm[];
    float* sIn = sm;                    // [32][4][66]
    float* sV  = sm + 32 * 4 * 66;      // [8][32][33]
    __shared__ float sS[32];

    const int cig = blockIdx.x;
    const int ty  = blockIdx.y;
    const int b   = blockIdx.z;
    const int ci0 = cig * 32;
    const int t   = threadIdx.x;

    if (t < 32) sS[t] = g_s[b * C_IN + ci0 + t];
    __syncthreads();

    for (int idx = t; idx < 32 * 4 * 66; idx += 256) {
        int ci = idx / 264, r = idx % 264, i = r / 66, xx = r % 66;
        int ys = 2 * ty - 1 + i, xs = xx - 1;
        float v = 0.f;
        if ((unsigned)ys < 64 && (unsigned)xs < 64)
            v = input[(((size_t)b * C_IN + ci0 + ci) * 64 + ys) * 64 + xs] * sS[ci];
        sIn[idx] = v;
    }
    __syncthreads();

    const int nt = b * 8 + (ty >> 2);
    const int nw = ty & 3;
    const int run = t >> 4;          // 0..15
    const int ks  = run >> 2;
    const int nf  = run & 3;
    const int off = (t & 15) * 4;

    for (int p = 0; p < 2; p++) {
        // ---- compute pass: all (ci,tx), store xinu in [p*8, p*8+8) ----
#pragma unroll
        for (int q = 0; q < 4; q++) {
            int pair = q * 256 + t;
            int ci = pair >> 5, tx = pair & 31;
            const float* dp = sIn + ci * 264 + 2 * tx;
            float z[4][4];
#pragma unroll
            for (int j = 0; j < 4; j++) {
                float d0 = dp[0 * 66 + j], d1 = dp[1 * 66 + j];
                float d2 = dp[2 * 66 + j], d3 = dp[3 * 66 + j];
                z[0][j] = d0 - d2; z[1][j] = d1 + d2;
                z[2][j] = d2 - d1; z[3][j] = d1 - d3;
            }
#pragma unroll
            for (int i = 0; i < 4; i++) {
                float vv[4];
                vv[0] = z[i][0] - z[i][2];
                vv[1] = z[i][1] + z[i][2];
                vv[2] = z[i][2] - z[i][1];
                vv[3] = z[i][1] - z[i][3];
#pragma unroll
                for (int j = 0; j < 4; j++) {
                    int xl = i * 4 + j - p * 8;
                    if (xl >= 0 && xl < 8)
                        sV[(xl * 32 + ci) * 33 + tx] = vv[j];
                }
            }
        }
        __syncthreads();
        // ---- gather-write pass (coalesced float4 stores) ----
#pragma unroll
        for (int xl = 0; xl < 8; xl++) {
            int xinu = p * 8 + xl;
            float* base = g_V + (((size_t)xinu * 128 + nt) * 16 + cig) * 4096;
            float v[4];
#pragma unroll
            for (int j = 0; j < 4; j++) {
                int le = off + j;
                int lane = le >> 1, e = le & 1;
                int lr = lane >> 2, lc = lane & 3;
                int kc = ks * 8 + e * 4 + lc;
                int tx = nf * 8 + lr;
                v[j] = to_tf32(sV[(xl * 32 + kc) * 33 + tx]);
            }
            int fidx = ((ks * 4 + nw) * 4 + nf) * 64 + off;
            *(float4*)&base[fidx] = make_float4(v[0], v[1], v[2], v[3]);
        }
        __syncthreads();
    }
}

// ---------------------------------------------------------------------------
// K5: 16 batched GEMMs. CTA: 128 co x 128 n, 8 warps (2Mx4N), warp 64x32,
// K=512 in 16 stages of 32. 3-stage ring, 96KB smem, 2 CTAs/SM.
// grid (4 ct, 128 nt, 16 xinu).
// ---------------------------------------------------------------------------
#define A_STAGE_B 16384
#define B_STAGE_B 16384
#define STAGE_B   (A_STAGE_B + B_STAGE_B)
#define NSTAGE    3
#define NS        16
#define DYN_SMEM  (NSTAGE * STAGE_B)        // 98304

__global__ __launch_bounds__(256, 2) void gemm_kernel() {
    extern __shared__ float smem[];
    const uint32_t sb = s2u(smem);
    const int t = threadIdx.x;
    const int w = t >> 5, lane = t & 31;
    const int mw = w >> 2;        // 0..1
    const int nw = w & 3;         // 0..3

    const int ct   = blockIdx.x;
    const int nt   = blockIdx.y;
    const int xinu = blockIdx.z;

    const float* Ab = g_U + ((size_t)xinu * 4 + ct) * 16 * 4096;
    const float* Xb = g_V + ((size_t)xinu * 128 + nt) * 16 * 4096;

    // A: 1024 cp16 chunks, B: 1024 chunks; 8 per thread
    auto load_stage = [&](int stage, int buf) {
        const uint32_t base = sb + buf * STAGE_B;
        const float* as = Ab + (size_t)stage * 4096;
        const float* xs = Xb + (size_t)stage * 4096;
#pragma unroll
        for (int j = 0; j < 4; j++) {
            int c = j * 256 + t;
            cp16(base + c * 16, as + c * 4);
        }
#pragma unroll
        for (int j = 0; j < 4; j++) {
            int c = j * 256 + t;
            cp16(base + A_STAGE_B + c * 16, xs + c * 4);
        }
        cp_commit();
    };

    float acc[4][4][4];
#pragma unroll
    for (int i = 0; i < 4; i++)
#pragma unroll
        for (int j = 0; j < 4; j++)
#pragma unroll
            for (int c = 0; c < 4; c++) acc[i][j][c] = 0.f;

    load_stage(0, 0);
    load_stage(1, 1);

    int bufc = 0;
    for (int i = 0; i < NS; i++) {
        cp_wait<1>();
        __syncthreads();
        if (i + 2 < NS) {
            int nb = bufc + 2; if (nb >= NSTAGE) nb -= NSTAGE;
            load_stage(i + 2, nb);
        }

        const float* As = smem + bufc * (STAGE_B / 4);
        const float* Bs = As + (A_STAGE_B / 4);

#pragma unroll
        for (int ks = 0; ks < 4; ks++) {
            uint4 a4[4];
            uint2 b2[4];
#pragma unroll
            for (int mf = 0; mf < 4; mf++)
                a4[mf] = *(const uint4*)(As + (((ks * 2 + mw) * 4 + mf) * 32 + lane) * 4);
#pragma unroll
            for (int nf = 0; nf < 4; nf++)
                b2[nf] = *(const uint2*)(Bs + (((ks * 4 + nw) * 4 + nf) * 32 + lane) * 2);
#pragma unroll
            for (int mf = 0; mf < 4; mf++)
#pragma unroll
                for (int nf = 0; nf < 4; nf++)
                    mma8(acc[mf][nf], (const uint32_t*)&a4[mf], (const uint32_t*)&b2[nf]);
        }
        bufc = (bufc + 1 == NSTAGE) ? 0 : bufc + 1;
    }

    // ---- epilogue: raw M ----
    const int lr = lane >> 2;
    const int lc = lane & 3;
    const size_t n0 = (size_t)nt * 128;
#pragma unroll
    for (int mf = 0; mf < 4; mf++) {
        const int coA = ct * 128 + mw * 64 + mf * 16 + lr;
        const int coB = coA + 8;
        float* opA = g_M + ((size_t)xinu * C_OUT + coA) * NTOT + n0;
        float* opB = g_M + ((size_t)xinu * C_OUT + coB) * NTOT + n0;
#pragma unroll
        for (int nf = 0; nf < 4; nf++) {
            const int px = nw * 32 + nf * 8 + lc * 2;
            float2 vA, vB;
            vA.x = acc[mf][nf][0]; vA.y = acc[mf][nf][1];
            vB.x = acc[mf][nf][2]; vB.y = acc[mf][nf][3];
            *(float2*)(opA + px) = vA;
            *(float2*)(opB + px) = vB;
        }
    }
}

// ---------------------------------------------------------------------------
// K6: output transform Y = A^T M A, scaled by demod*CONV_SCALE.
// grid (co 512, b 16), block 256: thread t -> ty=t>>3, tx0=(t&7)*4.
// ---------------------------------------------------------------------------
__global__ __launch_bounds__(256) void wino_out_kernel(float* __restrict__ out) {
    const int co = blockIdx.x, b = blockIdx.y;
    const int t = threadIdx.x;
    const int ty = t >> 3, tx0 = (t & 7) * 4;
    const size_t nbase = (size_t)b * 1024 + ty * 32 + tx0;

    float4 m[16];
#pragma unroll
    for (int xinu = 0; xinu < 16; xinu++)
        m[xinu] = *(const float4*)&g_M[((size_t)xinu * C_OUT + co) * NTOT + nbase];

    const float sc = g_demod[b * C_OUT + co] * CONV_SCALE;
    float r0[8], r1[8];
#pragma unroll
    for (int q = 0; q < 4; q++) {
        float z0[4], z1[4];
#pragma unroll
        for (int nu = 0; nu < 4; nu++) {
            float m0 = ((const float*)&m[0 * 4 + nu])[q];
            float m1 = ((const float*)&m[1 * 4 + nu])[q];
            float m2 = ((const float*)&m[2 * 4 + nu])[q];
            float m3 = ((const float*)&m[3 * 4 + nu])[q];
            z0[nu] = m0 + m1 + m2;
            z1[nu] = m1 - m2 - m3;
        }
        r0[q * 2 + 0] = (z0[0] + z0[1] + z0[2]) * sc;
        r0[q * 2 + 1] = (z0[1] - z0[2] - z0[3]) * sc;
        r1[q * 2 + 0] = (z1[0] + z1[1] + z1[2]) * sc;
        r1[q * 2 + 1] = (z1[1] - z1[2] - z1[3]) * sc;
    }

    float* op = out + (((size_t)b * C_OUT + co) * 64 + 2 * ty) * 64 + 2 * tx0;
    *(float4*)(op)      = make_float4(r0[0], r0[1], r0[2], r0[3]);
    *(float4*)(op + 4)  = make_float4(r0[4], r0[5], r0[6], r0[7]);
    *(float4*)(op + 64) = make_float4(r1[0], r1[1], r1[2], r1[3]);
    *(float4*)(op + 68) = make_float4(r1[4], r1[5], r1[6], r1[7]);
}

// ---------------------------------------------------------------------------
extern "C" void kernel_launch(void* const* d_in, const int* in_sizes, int n_in,
                              void* d_out, int out_size) {
    const float* input = (const float*)d_in[0];
    const float* style = (const float*)d_in[1];
    const float* convw = (const float*)d_in[2];
    const float* modw  = (const float*)d_in[3];
    const float* modb  = (const float*)d_in[4];
    float* out = (float*)d_out;

    static int init_done = 0;
    if (!init_done) {
        cudaFuncSetAttribute(gemm_kernel, cudaFuncAttributeMaxDynamicSharedMemorySize, DYN_SMEM);
        cudaFuncSetAttribute(wino_in_kernel, cudaFuncAttributeMaxDynamicSharedMemorySize, VIN_SMEM);
        init_done = 1;
    }

    style_kernel<<<B_, STYLE_D>>>(style, modw, modb);
    wsq_kernel<<<(C_OUT * C_IN + 511) / 512, 512>>>(convw);
    demod_kernel<<<B_, C_OUT>>>();
    wino_w_kernel<<<256, 256>>>(convw);
    wino_in_kernel<<<dim3(16, 32, 16), 256, VIN_SMEM>>>(input);
    gemm_kernel<<<dim3(4, 128, 16), 256, DYN_SMEM>>>();
    wino_out_kernel<<<dim3(C_OUT, B_), 256>>>(out);
}